// round 1
// baseline (speedup 1.0000x reference)
#include <cuda_runtime.h>
#include <cstdint>

#define DIN   512
#define DOUT  4096
#define CAP   96          // max nonzeros per output column (mean 25.6, +14 sd safety)

#define RB    64          // batch rows per GEMM CTA
#define WARPS 16
#define CPW   64          // columns per warp
#define XPITCH 66         // smem pitch for transposed x tile (even -> aligned float2)
#define OSP   9           // out-staging pitch

// ---------------- device scratch (static: allocation-free) ----------------
__device__ __align__(16) int2  g_list[DOUT * CAP];   // {idx, fp32 bits of W*mask}
__device__            int      g_nnz[DOUT];
__device__ __align__(16) float g_boost[DOUT];

// ---------------- kernel 1: compact sparse lists + boost ----------------
__global__ void k_prep(const float* __restrict__ W, const float* __restrict__ M,
                       const float* __restrict__ duty, const int* __restrict__ kptr) {
    int gt = blockIdx.x * blockDim.x + threadIdx.x;
    if (gt < DOUT) {
        float target = (float)(*kptr) / (float)DOUT;   // 205/4096, exact in fp32
        g_boost[gt] = expf(0.5f * (target - duty[gt]));
    }
    int j    = blockIdx.x * (blockDim.x >> 5) + (threadIdx.x >> 5);
    int lane = threadIdx.x & 31;
    if (j >= DOUT) return;
    const float* Wr = W + (size_t)j * DIN;
    const float* Mr = M + (size_t)j * DIN;
    int base = 0;
    for (int c = 0; c < DIN / 32; ++c) {
        int i = c * 32 + lane;
        float w = Wr[i] * Mr[i];                 // mask is exactly 0.0 or 1.0
        bool nz = (w != 0.0f);
        unsigned bal = __ballot_sync(0xffffffffu, nz);
        int pos = base + __popc(bal & ((1u << lane) - 1u));
        if (nz && pos < CAP)
            g_list[j * CAP + pos] = make_int2(i, __float_as_int(w));
        base += __popc(bal);
    }
    if (lane == 0) g_nnz[j] = (base < CAP) ? base : CAP;
}

// ---------------- kernel 2: sparse gather GEMM (fp32 exact) ----------------
__global__ void __launch_bounds__(32 * WARPS, 1)
k_gemm(const float* __restrict__ x, const float* __restrict__ bias,
       float* __restrict__ yout) {
    extern __shared__ float sm[];
    float* xs  = sm;                       // [DIN][XPITCH] transposed x tile
    float* os  = sm + DIN * XPITCH;        // [WARPS][RB][OSP] out staging
    int tid  = threadIdx.x;
    int w    = tid >> 5;
    int lane = tid & 31;
    int rowbase = blockIdx.x * RB;

    // load x tile [RB][DIN] transposed into smem (coalesced float4 reads)
    const float4* x4 = (const float4*)(x + (size_t)rowbase * DIN);
    for (int t = tid; t < RB * (DIN / 4); t += blockDim.x) {
        int r  = t >> 7;                   // DIN/4 == 128
        int i4 = t & 127;
        float4 v = x4[(size_t)r * (DIN / 4) + i4];
        int ib = i4 * 4;
        xs[(ib + 0) * XPITCH + r] = v.x;
        xs[(ib + 1) * XPITCH + r] = v.y;
        xs[(ib + 2) * XPITCH + r] = v.z;
        xs[(ib + 3) * XPITCH + r] = v.w;
    }
    __syncthreads();

    float* osw  = os + w * (RB * OSP);
    int jwarp   = blockIdx.y * (WARPS * CPW) + w * CPW;

    for (int g = 0; g < CPW / 8; ++g) {
        for (int cc = 0; cc < 8; ++cc) {
            int j = jwarp + g * 8 + cc;
            const int2* lst = &g_list[j * CAP];
            int nnz = g_nnz[j];
            float acc0 = 0.f, acc1 = 0.f;
            #pragma unroll 4
            for (int e = 0; e < nnz; ++e) {
                int2 p  = __ldg(&lst[e]);                       // broadcast load
                float v = __int_as_float(p.y);
                float2 xv = *(const float2*)&xs[p.x * XPITCH + 2 * lane];
                acc0 = fmaf(xv.x, v, acc0);                     // row 2*lane
                acc1 = fmaf(xv.y, v, acc1);                     // row 2*lane+1
            }
            float bj = __ldg(&bias[j]);
            osw[(2 * lane)     * OSP + cc] = acc0 + bj;
            osw[(2 * lane + 1) * OSP + cc] = acc1 + bj;
        }
        __syncwarp();
        // coalesced write of 64 rows x 8 cols (full 32B sectors)
        int j0 = jwarp + g * 8;
        #pragma unroll
        for (int q = 0; q < 4; ++q) {
            int chunk = q * 32 + lane;      // 0..127
            int row   = chunk >> 1;
            int c0    = (chunk & 1) * 4;
            float4 v;
            v.x = osw[row * OSP + c0 + 0];
            v.y = osw[row * OSP + c0 + 1];
            v.z = osw[row * OSP + c0 + 2];
            v.w = osw[row * OSP + c0 + 3];
            *(float4*)&yout[(size_t)(rowbase + row) * DOUT + j0 + c0] = v;
        }
        __syncwarp();
    }
}

// ---------------- kernel 3: per-row radix select + masked rewrite ----------------
__global__ void __launch_bounds__(256)
k_select(float* __restrict__ y, const int* __restrict__ kptr) {
    __shared__ float    ys[DOUT];
    __shared__ unsigned ks[DOUT];
    __shared__ unsigned hist[256];
    __shared__ unsigned s_prefix;
    __shared__ int      s_kk;

    int tid = threadIdx.x;
    size_t rowoff = (size_t)blockIdx.x * DOUT;
    const float4* y4 = (const float4*)(y + rowoff);
    const float4* b4 = (const float4*)g_boost;

    for (int t = tid; t < DOUT / 4; t += blockDim.x) {
        float4 v  = y4[t];
        float4 bo = b4[t];
        float bv[4] = { v.x * bo.x, v.y * bo.y, v.z * bo.z, v.w * bo.w };
        float vv[4] = { v.x, v.y, v.z, v.w };
        #pragma unroll
        for (int q = 0; q < 4; ++q) {
            ys[t * 4 + q] = vv[q];
            unsigned u = __float_as_uint(bv[q]);
            ks[t * 4 + q] = (u & 0x80000000u) ? ~u : (u | 0x80000000u);
        }
    }
    if (tid == 0) { s_prefix = 0u; s_kk = *kptr; }
    __syncthreads();

    for (int pass = 0; pass < 4; ++pass) {
        int shift = 24 - 8 * pass;
        unsigned prefix = s_prefix;
        int kk = s_kk;
        if (tid < 256) hist[tid] = 0u;
        __syncthreads();
        unsigned hi_mask = (pass == 0) ? 0u : (0xFFFFFFFFu << (shift + 8));
        for (int t = tid; t < DOUT; t += blockDim.x) {
            unsigned key = ks[t];
            bool act = ((key & hi_mask) == prefix);
            unsigned bal = __ballot_sync(0xffffffffu, act);
            if (act) {
                int bin = (key >> shift) & 255;
                unsigned mm = __match_any_sync(bal, bin);   // skew-safe aggregation
                int leader = __ffs(mm) - 1;
                if ((tid & 31) == leader) atomicAdd(&hist[bin], __popc(mm));
            }
        }
        __syncthreads();
        if (tid == 0) {
            int acc = 0, b = 255;
            for (; b >= 0; --b) {
                int nb = acc + (int)hist[b];
                if (nb >= kk) break;
                acc = nb;
            }
            s_prefix = prefix | ((unsigned)b << shift);
            s_kk = kk - acc;
        }
        __syncthreads();
    }

    unsigned thr = s_prefix;   // exact key of the k-th largest boosted value
    float4* yo4 = (float4*)(y + rowoff);
    for (int t = tid; t < DOUT / 4; t += blockDim.x) {
        float4 v;
        v.x = (ks[t * 4 + 0] >= thr) ? ys[t * 4 + 0] : 0.f;
        v.y = (ks[t * 4 + 1] >= thr) ? ys[t * 4 + 1] : 0.f;
        v.z = (ks[t * 4 + 2] >= thr) ? ys[t * 4 + 2] : 0.f;
        v.w = (ks[t * 4 + 3] >= thr) ? ys[t * 4 + 3] : 0.f;
        yo4[t] = v;
    }
}

// ---------------- launch ----------------
extern "C" void kernel_launch(void* const* d_in, const int* in_sizes, int n_in,
                              void* d_out, int out_size) {
    const float* x    = (const float*)d_in[0];
    const float* W    = (const float*)d_in[1];
    const float* b    = (const float*)d_in[2];
    const float* m    = (const float*)d_in[3];
    const float* duty = (const float*)d_in[4];
    const int*   k    = (const int*)d_in[5];
    float* out = (float*)d_out;

    int B = in_sizes[0] / DIN;   // 16384

    k_prep<<<DOUT / 8, 256>>>(W, m, duty, k);

    const int smem_bytes = (DIN * XPITCH + WARPS * RB * OSP) * (int)sizeof(float); // 172 KB
    cudaFuncSetAttribute(k_gemm, cudaFuncAttributeMaxDynamicSharedMemorySize, smem_bytes);
    dim3 grid(B / RB, DOUT / (WARPS * CPW));   // (256, 4)
    k_gemm<<<grid, 32 * WARPS, smem_bytes>>>(x, b, out);

    k_select<<<B, 256>>>(out, k);
}

// round 3
// speedup vs baseline: 1.2882x; 1.2882x over previous
#include <cuda_runtime.h>
#include <cstdint>

#define DIN   512
#define DOUT  4096
#define CAP   96          // max nonzeros per output column (mean 25.6, +14 sd safety)

#define RB    64          // batch rows per GEMM CTA
#define WARPS 16
#define CPW   64          // columns per warp
#define XPITCH 66         // smem pitch for transposed x tile (even -> aligned float2)
#define OSP   9           // out-staging pitch

// ---------------- device scratch (static: allocation-free) ----------------
__device__ __align__(16) int2  g_list[DOUT * CAP];   // {idx, fp32 bits of W*mask}
__device__            int      g_nnz[DOUT];
__device__ __align__(16) float g_boost[DOUT];

// ---------------- kernel 1: compact sparse lists + boost ----------------
__global__ void k_prep(const float* __restrict__ W, const float* __restrict__ M,
                       const float* __restrict__ duty, const int* __restrict__ kptr) {
    int gt = blockIdx.x * blockDim.x + threadIdx.x;
    if (gt < DOUT) {
        float target = (float)(*kptr) / (float)DOUT;   // 205/4096, exact in fp32
        g_boost[gt] = expf(0.5f * (target - duty[gt]));
    }
    int j    = blockIdx.x * (blockDim.x >> 5) + (threadIdx.x >> 5);
    int lane = threadIdx.x & 31;
    if (j >= DOUT) return;
    const float* Wr = W + (size_t)j * DIN;
    const float* Mr = M + (size_t)j * DIN;
    int base = 0;
    for (int c = 0; c < DIN / 32; ++c) {
        int i = c * 32 + lane;
        float w = Wr[i] * Mr[i];                 // mask is exactly 0.0 or 1.0
        bool nz = (w != 0.0f);
        unsigned bal = __ballot_sync(0xffffffffu, nz);
        int pos = base + __popc(bal & ((1u << lane) - 1u));
        if (nz && pos < CAP)
            g_list[j * CAP + pos] = make_int2(i, __float_as_int(w));
        base += __popc(bal);
    }
    if (lane == 0) g_nnz[j] = (base < CAP) ? base : CAP;
}

// ---------------- kernel 2: sparse gather GEMM (fp32 exact) ----------------
// List entries are fetched COALESCED into lane registers (double-buffered one
// column ahead), then broadcast per-element via SHFL.IDX: no global-load
// latency in the steady state; bound by L1tex wavefronts (LDS.64 gathers).
__global__ void __launch_bounds__(32 * WARPS, 1)
k_gemm(const float* __restrict__ x, const float* __restrict__ bias,
       float* __restrict__ yout) {
    extern __shared__ float sm[];
    float* xs  = sm;                       // [DIN][XPITCH] transposed x tile
    float* os  = sm + DIN * XPITCH;        // [WARPS][RB][OSP] out staging
    int tid  = threadIdx.x;
    int w    = tid >> 5;
    int lane = tid & 31;
    int rowbase = blockIdx.x * RB;

    // load x tile [RB][DIN] transposed into smem (coalesced float4 reads)
    const float4* x4 = (const float4*)(x + (size_t)rowbase * DIN);
    for (int t = tid; t < RB * (DIN / 4); t += blockDim.x) {
        int r  = t >> 7;                   // DIN/4 == 128
        int i4 = t & 127;
        float4 v = x4[(size_t)r * (DIN / 4) + i4];
        int ib = i4 * 4;
        xs[(ib + 0) * XPITCH + r] = v.x;
        xs[(ib + 1) * XPITCH + r] = v.y;
        xs[(ib + 2) * XPITCH + r] = v.z;
        xs[(ib + 3) * XPITCH + r] = v.w;
    }
    __syncthreads();

    float* osw  = os + w * (RB * OSP);
    int jwarp   = blockIdx.y * (WARPS * CPW) + w * CPW;
    float* xrow = xs + 2 * lane;

    // ---- software-pipelined column loop ----
    // prologue: fetch column 0's list (coalesced: lane e holds entry e)
    const long long* L0 = (const long long*)&g_list[(size_t)jwarp * CAP];
    long long pA = __ldg(L0 + lane);
    long long pB = __ldg(L0 + 32 + lane);
    int nnz = __ldg(&g_nnz[jwarp]);

    for (int ci = 0; ci < CPW; ++ci) {
        int j = jwarp + ci;
        // prefetch next column's list while we chew on this one
        int jn = jwarp + ((ci + 1 < CPW) ? (ci + 1) : ci);
        const long long* Ln = (const long long*)&g_list[(size_t)jn * CAP];
        long long nA = __ldg(Ln + lane);
        long long nB = __ldg(Ln + 32 + lane);
        int nnz_n   = __ldg(&g_nnz[jn]);

        float acc0 = 0.f, acc1 = 0.f;
        int n0 = (nnz < 32) ? nnz : 32;
        #pragma unroll 4
        for (int e = 0; e < n0; ++e) {
            long long p = __shfl_sync(0xffffffffu, pA, e);
            int   idx = (int)(unsigned)(p & 0xffffffffLL);
            float v   = __int_as_float((int)(p >> 32));
            float2 xv = *(const float2*)&xrow[idx * XPITCH];
            acc0 = fmaf(xv.x, v, acc0);
            acc1 = fmaf(xv.y, v, acc1);
        }
        if (nnz > 32) {
            int n1 = ((nnz < 64) ? nnz : 64) - 32;
            #pragma unroll 4
            for (int e = 0; e < n1; ++e) {
                long long p = __shfl_sync(0xffffffffu, pB, e);
                int   idx = (int)(unsigned)(p & 0xffffffffLL);
                float v   = __int_as_float((int)(p >> 32));
                float2 xv = *(const float2*)&xrow[idx * XPITCH];
                acc0 = fmaf(xv.x, v, acc0);
                acc1 = fmaf(xv.y, v, acc1);
            }
            // astronomically rare overflow (nnz>64): exact fallback
            for (int e = 64; e < nnz; ++e) {
                int2 p = __ldg(&g_list[(size_t)j * CAP + e]);
                float v = __int_as_float(p.y);
                float2 xv = *(const float2*)&xrow[p.x * XPITCH];
                acc0 = fmaf(xv.x, v, acc0);
                acc1 = fmaf(xv.y, v, acc1);
            }
        }
        float bj = __ldg(&bias[j]);
        int cc = ci & 7;
        osw[(2 * lane)     * OSP + cc] = acc0 + bj;
        osw[(2 * lane + 1) * OSP + cc] = acc1 + bj;

        pA = nA; pB = nB; nnz = nnz_n;

        if (cc == 7) {
            __syncwarp();
            // coalesced write of 64 rows x 8 cols (full 32B sectors)
            int j0 = jwarp + (ci & ~7);
            #pragma unroll
            for (int q = 0; q < 4; ++q) {
                int chunk = q * 32 + lane;      // 0..127
                int row   = chunk >> 1;
                int c0    = (chunk & 1) * 4;
                float4 v;
                v.x = osw[row * OSP + c0 + 0];
                v.y = osw[row * OSP + c0 + 1];
                v.z = osw[row * OSP + c0 + 2];
                v.w = osw[row * OSP + c0 + 3];
                *(float4*)&yout[(size_t)(rowbase + row) * DOUT + j0 + c0] = v;
            }
            __syncwarp();
        }
    }
}

// ---------------- kernel 3: per-row radix select + masked rewrite ----------------
__global__ void __launch_bounds__(256)
k_select(float* __restrict__ y, const int* __restrict__ kptr) {
    __shared__ float    ys[DOUT];
    __shared__ unsigned ks[DOUT];
    __shared__ unsigned hist[256];
    __shared__ unsigned s_prefix;
    __shared__ int      s_kk;

    int tid = threadIdx.x;
    size_t rowoff = (size_t)blockIdx.x * DOUT;
    const float4* y4 = (const float4*)(y + rowoff);
    const float4* b4 = (const float4*)g_boost;

    for (int t = tid; t < DOUT / 4; t += blockDim.x) {
        float4 v  = y4[t];
        float4 bo = b4[t];
        float bv[4] = { v.x * bo.x, v.y * bo.y, v.z * bo.z, v.w * bo.w };
        float vv[4] = { v.x, v.y, v.z, v.w };
        #pragma unroll
        for (int q = 0; q < 4; ++q) {
            ys[t * 4 + q] = vv[q];
            unsigned u = __float_as_uint(bv[q]);
            ks[t * 4 + q] = (u & 0x80000000u) ? ~u : (u | 0x80000000u);
        }
    }
    if (tid == 0) { s_prefix = 0u; s_kk = *kptr; }
    __syncthreads();

    for (int pass = 0; pass < 4; ++pass) {
        int shift = 24 - 8 * pass;
        unsigned prefix = s_prefix;
        int kk = s_kk;
        if (tid < 256) hist[tid] = 0u;
        __syncthreads();
        unsigned hi_mask = (pass == 0) ? 0u : (0xFFFFFFFFu << (shift + 8));
        for (int t = tid; t < DOUT; t += blockDim.x) {
            unsigned key = ks[t];
            bool act = ((key & hi_mask) == prefix);
            unsigned bal = __ballot_sync(0xffffffffu, act);
            if (act) {
                int bin = (key >> shift) & 255;
                unsigned mm = __match_any_sync(bal, bin);   // skew-safe aggregation
                int leader = __ffs(mm) - 1;
                if ((tid & 31) == leader) atomicAdd(&hist[bin], __popc(mm));
            }
        }
        __syncthreads();
        if (tid == 0) {
            int acc = 0, b = 255;
            for (; b >= 0; --b) {
                int nb = acc + (int)hist[b];
                if (nb >= kk) break;
                acc = nb;
            }
            s_prefix = prefix | ((unsigned)b << shift);
            s_kk = kk - acc;
        }
        __syncthreads();
    }

    unsigned thr = s_prefix;   // exact key of the k-th largest boosted value
    float4* yo4 = (float4*)(y + rowoff);
    for (int t = tid; t < DOUT / 4; t += blockDim.x) {
        float4 v;
        v.x = (ks[t * 4 + 0] >= thr) ? ys[t * 4 + 0] : 0.f;
        v.y = (ks[t * 4 + 1] >= thr) ? ys[t * 4 + 1] : 0.f;
        v.z = (ks[t * 4 + 2] >= thr) ? ys[t * 4 + 2] : 0.f;
        v.w = (ks[t * 4 + 3] >= thr) ? ys[t * 4 + 3] : 0.f;
        yo4[t] = v;
    }
}

// ---------------- launch ----------------
extern "C" void kernel_launch(void* const* d_in, const int* in_sizes, int n_in,
                              void* d_out, int out_size) {
    const float* x    = (const float*)d_in[0];
    const float* W    = (const float*)d_in[1];
    const float* b    = (const float*)d_in[2];
    const float* m    = (const float*)d_in[3];
    const float* duty = (const float*)d_in[4];
    const int*   k    = (const int*)d_in[5];
    float* out = (float*)d_out;

    int B = in_sizes[0] / DIN;   // 16384

    k_prep<<<DOUT / 8, 256>>>(W, m, duty, k);

    const int smem_bytes = (DIN * XPITCH + WARPS * RB * OSP) * (int)sizeof(float); // 172 KB
    cudaFuncSetAttribute(k_gemm, cudaFuncAttributeMaxDynamicSharedMemorySize, smem_bytes);
    dim3 grid(B / RB, DOUT / (WARPS * CPW));   // (256, 4)
    k_gemm<<<grid, 32 * WARPS, smem_bytes>>>(x, b, out);

    k_select<<<B, 256>>>(out, k);
}

// round 4
// speedup vs baseline: 1.4131x; 1.0970x over previous
#include <cuda_runtime.h>
#include <cstdint>

#define DIN   512
#define DOUT  4096
#define CAP   96          // max nonzeros per output column (mean 25.6, +14 sd safety)

#define RB    64          // batch rows per GEMM CTA
#define WARPS 16
#define CPW   64          // columns per warp
#define XPITCH 66         // smem pitch for transposed x tile (even -> aligned float2)
#define OSP   9           // out-staging pitch

// ---------------- device scratch (static: allocation-free) ----------------
// g_list entries: {byte offset idx*XPITCH*4, fp32 bits of W*mask}, padded to
// even count per column with exact {0, 0.0f} (adding 0.0 is fp32-exact).
__device__ __align__(16) int2  g_list[DOUT * CAP];
__device__            int      g_nnz[DOUT];
__device__ __align__(16) float g_boost[DOUT];

// ---------------- kernel 1: compact sparse lists + boost ----------------
__global__ void k_prep(const float* __restrict__ W, const float* __restrict__ M,
                       const float* __restrict__ duty, const int* __restrict__ kptr) {
    int gt = blockIdx.x * blockDim.x + threadIdx.x;
    if (gt < DOUT) {
        float target = (float)(*kptr) / (float)DOUT;   // 205/4096, exact in fp32
        g_boost[gt] = expf(0.5f * (target - duty[gt]));
    }
    int j    = blockIdx.x * (blockDim.x >> 5) + (threadIdx.x >> 5);
    int lane = threadIdx.x & 31;
    if (j >= DOUT) return;
    const float* Wr = W + (size_t)j * DIN;
    const float* Mr = M + (size_t)j * DIN;
    int base = 0;
    for (int c = 0; c < DIN / 32; ++c) {
        int i = c * 32 + lane;
        float w = Wr[i] * Mr[i];                 // mask is exactly 0.0 or 1.0
        bool nz = (w != 0.0f);
        unsigned bal = __ballot_sync(0xffffffffu, nz);
        int pos = base + __popc(bal & ((1u << lane) - 1u));
        if (nz && pos < CAP)
            g_list[j * CAP + pos] = make_int2(i * XPITCH * 4, __float_as_int(w));
        base += __popc(bal);
    }
    if (lane == 0) {
        int n = (base < CAP) ? base : CAP;
        if ((n & 1) && n < CAP) g_list[j * CAP + n] = make_int2(0, 0); // exact pad
        g_nnz[j] = n;
    }
}

// ---------------- kernel 2: sparse gather GEMM (fp32 exact) ----------------
// Per warp: column lists double-buffered in a 512B smem stage (coalesced LDG
// 2 columns ahead, STS 1 ahead). Inner loop reads entry PAIRS via one
// broadcast LDS.128, then 2x LDS.64 row-gathers + 4 FFMA. No shuffles.
__global__ void __launch_bounds__(32 * WARPS, 1)
k_gemm(const float* __restrict__ x, const float* __restrict__ bias,
       float* __restrict__ yout) {
    extern __shared__ float sm[];
    float* xs  = sm;                       // [DIN][XPITCH] transposed x tile
    float* os  = sm + DIN * XPITCH;        // [WARPS][RB][OSP] out staging
    int4*  stg = (int4*)(os + WARPS * RB * OSP); // [WARPS][2][32] entry pairs
    int tid  = threadIdx.x;
    int w    = tid >> 5;
    int lane = tid & 31;
    int rowbase = blockIdx.x * RB;

    // load x tile [RB][DIN] transposed into smem (coalesced float4 reads)
    const float4* x4 = (const float4*)(x + (size_t)rowbase * DIN);
    for (int t = tid; t < RB * (DIN / 4); t += blockDim.x) {
        int r  = t >> 7;                   // DIN/4 == 128
        int i4 = t & 127;
        float4 v = x4[(size_t)r * (DIN / 4) + i4];
        int ib = i4 * 4;
        xs[(ib + 0) * XPITCH + r] = v.x;
        xs[(ib + 1) * XPITCH + r] = v.y;
        xs[(ib + 2) * XPITCH + r] = v.z;
        xs[(ib + 3) * XPITCH + r] = v.w;
    }
    __syncthreads();

    float* osw  = os + w * (RB * OSP);
    int jwarp   = blockIdx.y * (WARPS * CPW) + w * CPW;
    const char* xbase = (const char*)xs + lane * 8;   // this lane's 2-row slot
    int2* stgw = (int2*)(stg + w * 64);               // two 32-int4 buffers

    // ---- software pipeline: regs hold col ci+2's list; stage holds ci, ci+1 ----
    const int2* L;
    L = &g_list[(size_t)jwarp * CAP];
    int2 rA = __ldg(L + lane), rB = __ldg(L + 32 + lane);
    int n_cur = __ldg(&g_nnz[jwarp]);
    stgw[lane] = rA; stgw[32 + lane] = rB;            // stage col 0 -> buf0
    L = &g_list[(size_t)(jwarp + 1) * CAP];
    rA = __ldg(L + lane); rB = __ldg(L + 32 + lane);  // col 1 in regs
    int n_nxt = __ldg(&g_nnz[jwarp + 1]);
    __syncwarp();

    for (int ci = 0; ci < CPW; ++ci) {
        int j = jwarp + ci;
        // stage col ci+1 from regs into the other buffer
        if (ci + 1 < CPW) {
            int2* sb = stgw + ((ci + 1) & 1) * 64;
            sb[lane] = rA; sb[32 + lane] = rB;
        }
        // prefetch col ci+2 into regs
        int n_pf = 0;
        if (ci + 2 < CPW) {
            L = &g_list[(size_t)(jwarp + ci + 2) * CAP];
            rA = __ldg(L + lane); rB = __ldg(L + 32 + lane);
            n_pf = __ldg(&g_nnz[jwarp + ci + 2]);
        }

        // process current column from its staged buffer
        const int4* sb4 = (const int4*)(stgw + (ci & 1) * 64);
        int nc = (n_cur < 64) ? n_cur : 64;
        int npairs = (nc + 1) >> 1;
        float acc0 = 0.f, acc1 = 0.f;
        #pragma unroll 4
        for (int p = 0; p < npairs; ++p) {
            int4 q = sb4[p];                          // LDS.128 broadcast
            float2 xv0 = *(const float2*)(xbase + q.x);
            float2 xv1 = *(const float2*)(xbase + q.z);
            float v0 = __int_as_float(q.y);
            float v1 = __int_as_float(q.w);
            acc0 = fmaf(xv0.x, v0, acc0);
            acc1 = fmaf(xv0.y, v0, acc1);
            acc0 = fmaf(xv1.x, v1, acc0);
            acc1 = fmaf(xv1.y, v1, acc1);
        }
        // astronomically rare overflow (nnz>64): exact global fallback
        if (n_cur > 64) {
            for (int e = 64; e < n_cur; ++e) {
                int2 pe = __ldg(&g_list[(size_t)j * CAP + e]);
                float v = __int_as_float(pe.y);
                float2 xv = *(const float2*)(xbase + pe.x);
                acc0 = fmaf(xv.x, v, acc0);
                acc1 = fmaf(xv.y, v, acc1);
            }
        }
        float bj = __ldg(&bias[j]);
        int cc = ci & 7;
        osw[(2 * lane)     * OSP + cc] = acc0 + bj;
        osw[(2 * lane + 1) * OSP + cc] = acc1 + bj;

        n_cur = n_nxt; n_nxt = n_pf;

        if (cc == 7) {
            __syncwarp();
            // coalesced write of 64 rows x 8 cols (full 32B sectors)
            int j0 = jwarp + (ci & ~7);
            #pragma unroll
            for (int q = 0; q < 4; ++q) {
                int chunk = q * 32 + lane;      // 0..127
                int row   = chunk >> 1;
                int c0    = (chunk & 1) * 4;
                float4 v;
                v.x = osw[row * OSP + c0 + 0];
                v.y = osw[row * OSP + c0 + 1];
                v.z = osw[row * OSP + c0 + 2];
                v.w = osw[row * OSP + c0 + 3];
                *(float4*)&yout[(size_t)(rowbase + row) * DOUT + j0 + c0] = v;
            }
        }
        __syncwarp();   // staged buffer handoff for next iteration
    }
}

// ---------------- kernel 3: per-row radix select + masked rewrite ----------------
__global__ void __launch_bounds__(256)
k_select(float* __restrict__ y, const int* __restrict__ kptr) {
    __shared__ float    ys[DOUT];
    __shared__ unsigned ks[DOUT];
    __shared__ unsigned hist[256];
    __shared__ unsigned s_prefix;
    __shared__ int      s_kk;

    int tid = threadIdx.x;
    size_t rowoff = (size_t)blockIdx.x * DOUT;
    const float4* y4 = (const float4*)(y + rowoff);
    const float4* b4 = (const float4*)g_boost;

    for (int t = tid; t < DOUT / 4; t += blockDim.x) {
        float4 v  = y4[t];
        float4 bo = b4[t];
        float bv[4] = { v.x * bo.x, v.y * bo.y, v.z * bo.z, v.w * bo.w };
        float vv[4] = { v.x, v.y, v.z, v.w };
        #pragma unroll
        for (int q = 0; q < 4; ++q) {
            ys[t * 4 + q] = vv[q];
            unsigned u = __float_as_uint(bv[q]);
            ks[t * 4 + q] = (u & 0x80000000u) ? ~u : (u | 0x80000000u);
        }
    }
    if (tid == 0) { s_prefix = 0u; s_kk = *kptr; }
    __syncthreads();

    for (int pass = 0; pass < 4; ++pass) {
        int shift = 24 - 8 * pass;
        unsigned prefix = s_prefix;
        int kk = s_kk;
        if (tid < 256) hist[tid] = 0u;
        __syncthreads();
        unsigned hi_mask = (pass == 0) ? 0u : (0xFFFFFFFFu << (shift + 8));
        for (int t = tid; t < DOUT; t += blockDim.x) {
            unsigned key = ks[t];
            bool act = ((key & hi_mask) == prefix);
            unsigned bal = __ballot_sync(0xffffffffu, act);
            if (act) {
                int bin = (key >> shift) & 255;
                unsigned mm = __match_any_sync(bal, bin);   // skew-safe aggregation
                int leader = __ffs(mm) - 1;
                if ((tid & 31) == leader) atomicAdd(&hist[bin], __popc(mm));
            }
        }
        __syncthreads();
        if (tid == 0) {
            int acc = 0, b = 255;
            for (; b >= 0; --b) {
                int nb = acc + (int)hist[b];
                if (nb >= kk) break;
                acc = nb;
            }
            s_prefix = prefix | ((unsigned)b << shift);
            s_kk = kk - acc;
        }
        __syncthreads();
    }

    unsigned thr = s_prefix;   // exact key of the k-th largest boosted value
    float4* yo4 = (float4*)(y + rowoff);
    for (int t = tid; t < DOUT / 4; t += blockDim.x) {
        float4 v;
        v.x = (ks[t * 4 + 0] >= thr) ? ys[t * 4 + 0] : 0.f;
        v.y = (ks[t * 4 + 1] >= thr) ? ys[t * 4 + 1] : 0.f;
        v.z = (ks[t * 4 + 2] >= thr) ? ys[t * 4 + 2] : 0.f;
        v.w = (ks[t * 4 + 3] >= thr) ? ys[t * 4 + 3] : 0.f;
        yo4[t] = v;
    }
}

// ---------------- launch ----------------
extern "C" void kernel_launch(void* const* d_in, const int* in_sizes, int n_in,
                              void* d_out, int out_size) {
    const float* x    = (const float*)d_in[0];
    const float* W    = (const float*)d_in[1];
    const float* b    = (const float*)d_in[2];
    const float* m    = (const float*)d_in[3];
    const float* duty = (const float*)d_in[4];
    const int*   k    = (const int*)d_in[5];
    float* out = (float*)d_out;

    int B = in_sizes[0] / DIN;   // 16384

    k_prep<<<DOUT / 8, 256>>>(W, m, duty, k);

    const int smem_bytes = (DIN * XPITCH + WARPS * RB * OSP) * (int)sizeof(float)
                         + WARPS * 2 * 32 * (int)sizeof(int4);   // 172KB + 16KB
    cudaFuncSetAttribute(k_gemm, cudaFuncAttributeMaxDynamicSharedMemorySize, smem_bytes);
    dim3 grid(B / RB, DOUT / (WARPS * CPW));   // (256, 4)
    k_gemm<<<grid, 32 * WARPS, smem_bytes>>>(x, b, out);

    k_select<<<B, 256>>>(out, k);
}